// round 2
// baseline (speedup 1.0000x reference)
#include <cuda_runtime.h>
#include <math.h>
#include <stdint.h>

// Problem dims
static const int NB  = 128;
static const int TT  = 1024;   // T == TC
static const int NL  = 4;
static const int NVT = 50000;
static const int NE  = 256;
static const int NH  = 512;
static const int NVO = 50050;  // VT + MAX_OOV

// ---------------- scratch (single __device__ array, offsets in floats) ----
static const size_t OFF_X      = 0;                       // B*E
static const size_t OFF_GATES  = OFF_X      + (size_t)NB*NE;      // B*4H
static const size_t OFF_DEC    = OFF_GATES  + (size_t)NB*4*NH;    // B*H
static const size_t OFF_D1     = OFF_DEC    + (size_t)NB*NH;
static const size_t OFF_D2     = OFF_D1     + (size_t)NB*NH;
static const size_t OFF_CTX    = OFF_D2     + (size_t)NB*NH;
static const size_t OFF_CCTX   = OFF_CTX    + (size_t)NB*NH;
static const size_t OFF_CSC    = OFF_CCTX   + (size_t)NB*NH;      // B*TC
static const size_t OFF_PGEN   = OFF_CSC    + (size_t)NB*TT;      // B
static const size_t OFF_RMAX   = OFF_PGEN   + NB;                 // B
static const size_t OFF_RSUM   = OFF_RMAX   + NB;                 // B
static const size_t OFF_LOGITS = OFF_RSUM   + NB;                 // B*VT
static const size_t OFF_PCOPY  = OFF_LOGITS + (size_t)NB*NVT;     // B*VO
static const size_t SCRATCH_SZ = OFF_PCOPY  + (size_t)NB*NVO;

__device__ float g_scratch[SCRATCH_SZ];

// ---------------- zero p_copy ----------------
__global__ void zero_kernel(float* p, int n) {
    for (int i = blockIdx.x * blockDim.x + threadIdx.x; i < n; i += gridDim.x * blockDim.x)
        p[i] = 0.f;
}

// ---------------- embed: x = tanh(mean of 4 emb rows) ----------------
__global__ void embed_kernel(const int* __restrict__ ids,
                             const float* __restrict__ emb,
                             float* __restrict__ x_out) {
    int b = blockIdx.x, e = threadIdx.x;   // 256 threads
    float s = 0.f;
#pragma unroll
    for (int l = 0; l < NL; l++)
        s += emb[(size_t)ids[b * NL + l] * NE + e];
    x_out[b * NE + e] = tanhf(s * (1.0f / NL));
}

// ---------------- generic SGEMM NT:  C[128 x N] = A[128 x K] * W[N x K]^T ----
// TN = columns per thread, block covers 128 rows x 16*TN cols, 256 threads.
template <int TN>
__global__ __launch_bounds__(256)
void gemm_nt(const float* __restrict__ A, int lda,
             const float* __restrict__ W, int ldw,
             const float* __restrict__ bias,
             float* __restrict__ C, int ldc,
             int N, int K, int accumulate) {
    const int BN = 16 * TN;
    __shared__ float As[16][129];
    __shared__ float Ws[16][BN + 1];
    int tid = threadIdx.x;
    int tm = tid & 15;       // row group: rows tm + 16*r
    int tn = tid >> 4;       // col group: cols jb + tn*TN + u
    int jb = blockIdx.x * BN;

    float acc[8][TN];
#pragma unroll
    for (int r = 0; r < 8; r++)
#pragma unroll
        for (int u = 0; u < TN; u++) acc[r][u] = 0.f;

    for (int k0 = 0; k0 < K; k0 += 16) {
        __syncthreads();
#pragma unroll
        for (int n = 0; n < 8; n++) {            // A tile: 128 x 16
            int idx = tid + n * 256;
            int row = idx >> 4, kk = idx & 15;
            As[kk][row] = A[row * lda + k0 + kk];
        }
#pragma unroll
        for (int n = 0; n < TN; n++) {           // W tile: BN x 16
            int idx = tid + n * 256;
            int j = idx >> 4, kk = idx & 15;
            int jg = jb + j;
            Ws[kk][j] = (jg < N) ? W[(size_t)jg * ldw + k0 + kk] : 0.f;
        }
        __syncthreads();
#pragma unroll
        for (int k = 0; k < 16; k++) {
            float a[8], w[TN];
#pragma unroll
            for (int r = 0; r < 8; r++) a[r] = As[k][tm + 16 * r];
#pragma unroll
            for (int u = 0; u < TN; u++) w[u] = Ws[k][tn * TN + u];
#pragma unroll
            for (int r = 0; r < 8; r++)
#pragma unroll
                for (int u = 0; u < TN; u++) acc[r][u] += a[r] * w[u];
        }
    }
#pragma unroll
    for (int r = 0; r < 8; r++)
#pragma unroll
        for (int u = 0; u < TN; u++) {
            int j = jb + tn * TN + u;
            if (j < N) {
                int i = tm + 16 * r;
                float v = acc[r][u];
                if (bias) v += bias[j];
                size_t o = (size_t)i * ldc + j;
                if (accumulate) v += C[o];
                C[o] = v;
            }
        }
}

// ---------------- LSTM pointwise ----------------
__device__ __forceinline__ float sigm(float x) { return 1.f / (1.f + __expf(-x)); }

__global__ void lstm_kernel(const float* __restrict__ gates,
                            const float* __restrict__ c0,
                            const float* __restrict__ b_ih,
                            const float* __restrict__ b_hh,
                            float* __restrict__ dec,
                            float* __restrict__ out, int write_hc) {
    int b = blockIdx.x, j = threadIdx.x;  // 512 threads
    const float* g = gates + (size_t)b * 4 * NH;
    float ig = g[j]          + b_ih[j]          + b_hh[j];
    float fg = g[NH + j]     + b_ih[NH + j]     + b_hh[NH + j];
    float gg = g[2 * NH + j] + b_ih[2 * NH + j] + b_hh[2 * NH + j];
    float og = g[3 * NH + j] + b_ih[3 * NH + j] + b_hh[3 * NH + j];
    float c = sigm(fg) * c0[b * NH + j] + sigm(ig) * tanhf(gg);
    float h = sigm(og) * tanhf(c);
    dec[b * NH + j] = h;
    if (write_hc) {
        out[(size_t)NB * NVO + (size_t)b * NH + j] = h;
        out[(size_t)NB * NVO + (size_t)NB * NH + (size_t)b * NH + j] = c;
    }
}

// ---------------- single-pass flash attention over (B, T, H) --------------
// One block per batch row; 16 warps, each owns 64 rows, online softmax.
template <bool STORE_SCORES>
__global__ __launch_bounds__(512)
void attn_kernel(const float* __restrict__ enc,
                 const float* __restrict__ d,
                 float* __restrict__ ctx_out,
                 float* __restrict__ scores_out) {
    int b = blockIdx.x;
    int tid = threadIdx.x, wid = tid >> 5, lane = tid & 31;
    __shared__ float s_s[TT];
    __shared__ float s_m[16], s_l[16];
    __shared__ float s_ctx[NH];
    __shared__ float s_mg, s_lg;

    // d vector: each lane holds 16 components at q*128 + lane*4 + u
    float dreg[16];
    const float* dp = d + (size_t)b * NH;
#pragma unroll
    for (int q = 0; q < 4; q++) {
        float4 v = *(const float4*)(dp + q * 128 + lane * 4);
        dreg[q * 4 + 0] = v.x; dreg[q * 4 + 1] = v.y;
        dreg[q * 4 + 2] = v.z; dreg[q * 4 + 3] = v.w;
    }

    float m = -INFINITY, l = 0.f, acc[16];
#pragma unroll
    for (int i = 0; i < 16; i++) acc[i] = 0.f;

    const float* ep = enc + (size_t)b * TT * NH;
    int tbeg = wid * 64;
    for (int t0 = tbeg; t0 < tbeg + 64; t0 += 2) {
        float e0[16], e1[16];
        const float* r0 = ep + (size_t)t0 * NH;
        const float* r1 = r0 + NH;
#pragma unroll
        for (int q = 0; q < 4; q++) {
            float4 v0 = *(const float4*)(r0 + q * 128 + lane * 4);
            float4 v1 = *(const float4*)(r1 + q * 128 + lane * 4);
            e0[q*4+0]=v0.x; e0[q*4+1]=v0.y; e0[q*4+2]=v0.z; e0[q*4+3]=v0.w;
            e1[q*4+0]=v1.x; e1[q*4+1]=v1.y; e1[q*4+2]=v1.z; e1[q*4+3]=v1.w;
        }
        float sc0 = 0.f, sc1 = 0.f;
#pragma unroll
        for (int i = 0; i < 16; i++) { sc0 += e0[i] * dreg[i]; sc1 += e1[i] * dreg[i]; }
#pragma unroll
        for (int o = 16; o > 0; o >>= 1) {
            sc0 += __shfl_xor_sync(0xffffffffu, sc0, o);
            sc1 += __shfl_xor_sync(0xffffffffu, sc1, o);
        }
        if (lane == 0) { s_s[t0] = sc0; s_s[t0 + 1] = sc1; }
        // online update row 0
        {
            float mn = fmaxf(m, sc0);
            float corr = __expf(m - mn);
            float p = __expf(sc0 - mn);
            l = l * corr + p;
#pragma unroll
            for (int i = 0; i < 16; i++) acc[i] = acc[i] * corr + p * e0[i];
            m = mn;
        }
        // online update row 1
        {
            float mn = fmaxf(m, sc1);
            float corr = __expf(m - mn);
            float p = __expf(sc1 - mn);
            l = l * corr + p;
#pragma unroll
            for (int i = 0; i < 16; i++) acc[i] = acc[i] * corr + p * e1[i];
            m = mn;
        }
    }
    if (lane == 0) { s_m[wid] = m; s_l[wid] = l; }
    for (int i = tid; i < NH; i += 512) s_ctx[i] = 0.f;
    __syncthreads();
    if (tid == 0) {
        float mg = -INFINITY;
#pragma unroll
        for (int w = 0; w < 16; w++) mg = fmaxf(mg, s_m[w]);
        float lg = 0.f;
#pragma unroll
        for (int w = 0; w < 16; w++) lg += s_l[w] * __expf(s_m[w] - mg);
        s_mg = mg; s_lg = lg;
    }
    __syncthreads();
    float f = __expf(m - s_mg);
#pragma unroll
    for (int q = 0; q < 4; q++)
#pragma unroll
        for (int u = 0; u < 4; u++)
            atomicAdd(&s_ctx[q * 128 + lane * 4 + u], acc[q * 4 + u] * f);
    __syncthreads();
    float inv = 1.0f / s_lg;
    for (int i = tid; i < NH; i += 512) ctx_out[(size_t)b * NH + i] = s_ctx[i] * inv;
    if (STORE_SCORES) {
        float mg = s_mg;
        for (int t = tid; t < TT; t += 512)
            scores_out[(size_t)b * TT + t] = __expf(s_s[t] - mg) * inv;
    }
}

// ---------------- scatter-add copy distribution ----------------
__global__ void scatter_kernel(const int* __restrict__ cinp,
                               const float* __restrict__ cscores,
                               float* __restrict__ pcopy) {
    int i = blockIdx.x * blockDim.x + threadIdx.x;  // B*TC threads
    int b = i >> 10;
    atomicAdd(&pcopy[(size_t)b * NVO + cinp[i]], cscores[i]);
}

// ---------------- p_gen ----------------
__global__ void pgen_kernel(const float* __restrict__ ctx,
                            const float* __restrict__ cctx,
                            const float* __restrict__ dec,
                            const float* __restrict__ x,
                            const float* __restrict__ genW,
                            const float* __restrict__ genb,
                            const float* __restrict__ sigb,
                            const int* __restrict__ cinp,
                            float* __restrict__ pgen) {
    int b = blockIdx.x, tid = threadIdx.x;  // 256 threads
    const int F = 3 * NH + NE;
    float s = 0.f;
    for (int k = tid; k < F; k += 256) {
        float fv;
        if (k < NH)            fv = ctx[b * NH + k];
        else if (k < 2 * NH)   fv = cctx[b * NH + k - NH];
        else if (k < 3 * NH)   fv = dec[b * NH + k - 2 * NH];
        else                   fv = x[b * NE + k - 3 * NH];
        s += genW[k] * fv;
    }
    int cnt = 0;
    for (int t = tid; t < TT; t += 256) cnt += (cinp[b * TT + t] > 0);
    __shared__ float ss[256];
    __shared__ int   sc[256];
    ss[tid] = s; sc[tid] = cnt;
    __syncthreads();
    for (int o = 128; o > 0; o >>= 1) {
        if (tid < o) { ss[tid] += ss[tid + o]; sc[tid] += sc[tid + o]; }
        __syncthreads();
    }
    if (tid == 0) {
        float pg = 1.f / (1.f + __expf(-(ss[0] + genb[0] + sigb[0])));
        if (sc[0] == 0) pg = 1.f;
        pgen[b] = pg;
    }
}

// ---------------- vocab softmax reduction (max + sum) ----------------
__global__ void vred_kernel(const float* __restrict__ logits,
                            float* __restrict__ rmax, float* __restrict__ rsum) {
    int b = blockIdx.x, tid = threadIdx.x;  // 256 threads
    float m = -INFINITY, l = 0.f;
    const float* row = logits + (size_t)b * NVT;
    for (int v = tid; v < NVT; v += 256) {
        float xv = row[v];
        if (xv > m) { l = l * __expf(m - xv) + 1.f; m = xv; }
        else        { l += __expf(xv - m); }
    }
#pragma unroll
    for (int o = 16; o > 0; o >>= 1) {
        float m2 = __shfl_xor_sync(0xffffffffu, m, o);
        float l2 = __shfl_xor_sync(0xffffffffu, l, o);
        float mn = fmaxf(m, m2);
        l = l * __expf(m - mn) + l2 * __expf(m2 - mn);
        m = mn;
    }
    __shared__ float sm[8], sl[8];
    if ((tid & 31) == 0) { sm[tid >> 5] = m; sl[tid >> 5] = l; }
    __syncthreads();
    if (tid == 0) {
        float M = sm[0];
#pragma unroll
        for (int w = 1; w < 8; w++) M = fmaxf(M, sm[w]);
        float Ls = 0.f;
#pragma unroll
        for (int w = 0; w < 8; w++) Ls += sl[w] * __expf(sm[w] - M);
        rmax[b] = M; rsum[b] = Ls;
    }
}

// ---------------- final merge: log(pgen*pvocab + (1-pgen)*pcopy) ----------
__global__ void final_kernel(const float* __restrict__ logits,
                             const float* __restrict__ rmax,
                             const float* __restrict__ rsum,
                             const float* __restrict__ pgen,
                             const float* __restrict__ pcopy,
                             float* __restrict__ out) {
    int i = blockIdx.x * blockDim.x + threadIdx.x;
    if (i >= NB * NVO) return;
    int b = i / NVO;
    int v = i - b * NVO;
    float pg = pgen[b];
    float pv = 0.f;
    if (v < NVT)
        pv = __expf(logits[(size_t)b * NVT + v] - rmax[b]) / rsum[b];
    float p = pg * pv + (1.f - pg) * pcopy[i];
    out[i] = __logf(fmaxf(p, 1e-10f));
}

// ---------------- launcher ----------------
extern "C" void kernel_launch(void* const* d_in, const int* in_sizes, int n_in,
                              void* d_out, int out_size) {
    const int*   ids    = (const int*)d_in[0];
    const float* h0     = (const float*)d_in[1];
    const float* c0     = (const float*)d_in[2];
    const float* enc    = (const float*)d_in[3];
    const float* cenc   = (const float*)d_in[4];
    const int*   cinp   = (const int*)d_in[5];
    const float* emb    = (const float*)d_in[6];
    const float* W_ih   = (const float*)d_in[7];
    const float* W_hh   = (const float*)d_in[8];
    const float* b_ih   = (const float*)d_in[9];
    const float* b_hh   = (const float*)d_in[10];
    const float* attn_W = (const float*)d_in[11];
    const float* attn_b = (const float*)d_in[12];
    const float* cattn_W= (const float*)d_in[13];
    const float* cattn_b= (const float*)d_in[14];
    const float* gen_W  = (const float*)d_in[15];
    const float* gen_b  = (const float*)d_in[16];
    const float* sig_b  = (const float*)d_in[17];
    const float* out_W  = (const float*)d_in[18];
    const float* out_b  = (const float*)d_in[19];
    float* out = (float*)d_out;

    void* sp = nullptr;
    cudaGetSymbolAddress(&sp, g_scratch);
    float* S = (float*)sp;
    float* X      = S + OFF_X;
    float* GATES  = S + OFF_GATES;
    float* DEC    = S + OFF_DEC;
    float* D1     = S + OFF_D1;
    float* D2     = S + OFF_D2;
    float* CTX    = S + OFF_CTX;
    float* CCTX   = S + OFF_CCTX;
    float* CSC    = S + OFF_CSC;
    float* PGEN   = S + OFF_PGEN;
    float* RMAX   = S + OFF_RMAX;
    float* RSUM   = S + OFF_RSUM;
    float* LOGITS = S + OFF_LOGITS;
    float* PCOPY  = S + OFF_PCOPY;

    int write_hc = (out_size >= NB * NVO + 2 * NB * NH) ? 1 : 0;

    // 1. zero copy-distribution buffer
    zero_kernel<<<2048, 1024>>>(PCOPY, NB * NVO);
    // 2. embedding
    embed_kernel<<<NB, 256>>>(ids, emb, X);
    // 3. LSTM gates = x @ W_ih^T + h0 @ W_hh^T
    gemm_nt<1><<<(4 * NH + 15) / 16, 256>>>(X, NE, W_ih, NE, nullptr, GATES, 4 * NH, 4 * NH, NE, 0);
    gemm_nt<1><<<(4 * NH + 15) / 16, 256>>>(h0, NH, W_hh, NH, nullptr, GATES, 4 * NH, 4 * NH, NH, 1);
    // 4. LSTM pointwise -> dec, h_new, c_new
    lstm_kernel<<<NB, NH>>>(GATES, c0, b_ih, b_hh, DEC, out, write_hc);
    // 5. logits GEMM (biggest): 128 x 50000 x 512
    gemm_nt<4><<<(NVT + 63) / 64, 256>>>(DEC, NH, out_W, NH, out_b, LOGITS, NVT, NVT, NH, 0);
    // 6. d1, d2 projections
    gemm_nt<1><<<(NH + 15) / 16, 256>>>(DEC, NH, attn_W, NH, attn_b, D1, NH, NH, NH, 0);
    gemm_nt<1><<<(NH + 15) / 16, 256>>>(DEC, NH, cattn_W, NH, cattn_b, D2, NH, NH, NH, 0);
    // 7. attentions (single-pass flash)
    attn_kernel<false><<<NB, 512>>>(enc, D1, CTX, nullptr);
    attn_kernel<true ><<<NB, 512>>>(cenc, D2, CCTX, CSC);
    // 8. scatter copy scores
    scatter_kernel<<<(NB * TT) / 256, 256>>>(cinp, CSC, PCOPY);
    // 9. p_gen
    pgen_kernel<<<NB, 256>>>(CTX, CCTX, DEC, X, gen_W, gen_b, sig_b, cinp, PGEN);
    // 10. vocab softmax stats
    vred_kernel<<<NB, 256>>>(LOGITS, RMAX, RSUM);
    // 11. final merge + log
    final_kernel<<<(NB * NVO + 255) / 256, 256>>>(LOGITS, RMAX, RSUM, PGEN, PCOPY, out);
}

// round 6
// speedup vs baseline: 1.9877x; 1.9877x over previous
#include <cuda_runtime.h>
#include <cuda_bf16.h>
#include <math.h>
#include <stdint.h>

// Problem dims
static const int NB  = 128;
static const int TT  = 1024;   // T == TC
static const int NL  = 4;
static const int NVT = 50000;
static const int NE  = 256;
static const int NH  = 512;
static const int NVO = 50050;  // VT + MAX_OOV

// ---------------- scratch (single __device__ array, offsets in floats) ----
static const size_t OFF_X      = 0;                               // B*E
static const size_t OFF_GATES  = OFF_X      + (size_t)NB*NE;      // B*4H
static const size_t OFF_DEC    = OFF_GATES  + (size_t)NB*4*NH;    // B*H
static const size_t OFF_D1     = OFF_DEC    + (size_t)NB*NH;
static const size_t OFF_D2     = OFF_D1     + (size_t)NB*NH;
static const size_t OFF_CTX    = OFF_D2     + (size_t)NB*NH;
static const size_t OFF_CCTX   = OFF_CTX    + (size_t)NB*NH;
static const size_t OFF_CSC    = OFF_CCTX   + (size_t)NB*NH;      // B*TC
static const size_t OFF_PGEN   = OFF_CSC    + (size_t)NB*TT;      // B
static const size_t OFF_RMAX   = OFF_PGEN   + NB;                 // B
static const size_t OFF_RSUM   = OFF_RMAX   + NB;                 // B
static const size_t OFF_PAD    = OFF_RSUM   + NB + 64;            // align
static const size_t OFF_LOGITS = (OFF_PAD + 63) & ~(size_t)63;    // B*VT
static const size_t OFF_PCOPY  = OFF_LOGITS + (size_t)NB*NVT;     // B*VO
static const size_t OFF_DECBF  = ((OFF_PCOPY + (size_t)NB*NVO) + 63) & ~(size_t)63;  // B*NH bf16
static const size_t SCRATCH_SZ = OFF_DECBF + (size_t)NB*NH/2 + 64;

__device__ float g_scratch[SCRATCH_SZ];

#define SWZ(o) ((o) ^ (((o) >> 3) & 0x70))

// ---------------- zero ----------------
__global__ void zero_kernel(float* p, int n) {
    for (int i = blockIdx.x * blockDim.x + threadIdx.x; i < n; i += gridDim.x * blockDim.x)
        p[i] = 0.f;
}

// ---------------- fp32 -> bf16 convert (vectorized) ----------------
__global__ void f2bf_kernel(const float4* __restrict__ in, __nv_bfloat162* __restrict__ out, int n4) {
    for (int i = blockIdx.x * blockDim.x + threadIdx.x; i < n4; i += gridDim.x * blockDim.x) {
        float4 v = in[i];
        out[2 * i]     = __floats2bfloat162_rn(v.x, v.y);
        out[2 * i + 1] = __floats2bfloat162_rn(v.z, v.w);
    }
}

// ---------------- embed: x = tanh(mean of 4 emb rows) ----------------
__global__ void embed_kernel(const int* __restrict__ ids,
                             const float* __restrict__ emb,
                             float* __restrict__ x_out) {
    int b = blockIdx.x, e = threadIdx.x;   // 256 threads
    float s = 0.f;
#pragma unroll
    for (int l = 0; l < NL; l++)
        s += emb[(size_t)ids[b * NL + l] * NE + e];
    x_out[b * NE + e] = tanhf(s * (1.0f / NL));
}

// ---------------- skinny fp32 GEMM: C[128 x N] += A[128 x K] * W[N x K]^T
template <int SPLITK>
__global__ __launch_bounds__(256)
void gemm_skinny(const float* __restrict__ A, int lda,
                 const float* __restrict__ W, int ldw,
                 const float* __restrict__ bias,
                 float* __restrict__ C, int ldc,
                 int N, int K) {
    __shared__ float As[16][65];
    __shared__ float Ws[16][33];
    int tid = threadIdx.x;
    int tm = tid & 15;
    int tn = tid >> 4;
    int mb = blockIdx.y * 64;
    int jb = blockIdx.x * 32;
    int kchunk = K / SPLITK;
    int kbeg = blockIdx.z * kchunk;

    float acc[4][2] = {};
    for (int k0 = kbeg; k0 < kbeg + kchunk; k0 += 16) {
        __syncthreads();
#pragma unroll
        for (int i = 0; i < 4; i++) {
            int idx = tid + i * 256;
            int row = idx >> 4, kk = idx & 15;
            As[kk][row] = A[(size_t)(mb + row) * lda + k0 + kk];
        }
#pragma unroll
        for (int i = 0; i < 2; i++) {
            int idx = tid + i * 256;
            int j = idx >> 4, kk = idx & 15;
            Ws[kk][j] = W[(size_t)(jb + j) * ldw + k0 + kk];
        }
        __syncthreads();
#pragma unroll
        for (int k = 0; k < 16; k++) {
            float a[4], w0 = Ws[k][tn * 2], w1 = Ws[k][tn * 2 + 1];
#pragma unroll
            for (int r = 0; r < 4; r++) a[r] = As[k][tm + 16 * r];
#pragma unroll
            for (int r = 0; r < 4; r++) { acc[r][0] += a[r] * w0; acc[r][1] += a[r] * w1; }
        }
    }
#pragma unroll
    for (int r = 0; r < 4; r++)
#pragma unroll
        for (int u = 0; u < 2; u++) {
            int j = jb + tn * 2 + u;
            int i = mb + tm + 16 * r;
            float v = acc[r][u];
            if (bias && blockIdx.z == 0) v += bias[j];
            atomicAdd(&C[(size_t)i * ldc + j], v);
        }
}

// ---------------- LSTM pointwise ----------------
__device__ __forceinline__ float sigm(float x) { return 1.f / (1.f + __expf(-x)); }

__global__ void lstm_kernel(const float* __restrict__ gates,
                            const float* __restrict__ c0,
                            const float* __restrict__ b_ih,
                            const float* __restrict__ b_hh,
                            float* __restrict__ dec,
                            float* __restrict__ out, int write_hc) {
    int b = blockIdx.x, j = threadIdx.x;  // 512 threads
    const float* g = gates + (size_t)b * 4 * NH;
    float ig = g[j]          + b_ih[j]          + b_hh[j];
    float fg = g[NH + j]     + b_ih[NH + j]     + b_hh[NH + j];
    float gg = g[2 * NH + j] + b_ih[2 * NH + j] + b_hh[2 * NH + j];
    float og = g[3 * NH + j] + b_ih[3 * NH + j] + b_hh[3 * NH + j];
    float c = sigm(fg) * c0[b * NH + j] + sigm(ig) * tanhf(gg);
    float h = sigm(og) * tanhf(c);
    dec[b * NH + j] = h;
    if (write_hc) {
        out[(size_t)NB * NVO + (size_t)b * NH + j] = h;
        out[(size_t)NB * NVO + (size_t)NB * NH + (size_t)b * NH + j] = c;
    }
}

// ---------------- logits GEMM via bf16 mma.sync, fused fp32->bf16 B load --
// C[128 x 50000] = A[128x512]bf16 @ B[50000x512]fp32^T + bias, fp32 accum.
// A fully staged via cp.async (128KB). B: per 64-k chunk, each thread LDGs
// 8 fp32 float4s, converts to bf16, STS into double-buffered swizzled smem.
__global__ __launch_bounds__(256, 1)
void logits_mma(const __nv_bfloat16* __restrict__ A,
                const float* __restrict__ B,
                const float* __restrict__ bias,
                float* __restrict__ C) {
    extern __shared__ char smem[];
    const int tid = threadIdx.x, lane = tid & 31, wid = tid >> 5;
    const int wm = wid >> 2, wn = wid & 3;
    const int nblk = blockIdx.x * 128;
    uint32_t sA = (uint32_t)__cvta_generic_to_shared(smem);
    uint32_t sB = sA + 131072;

    // stage all of A: 8 chunks of [128 rows][128B], swizzled
#pragma unroll
    for (int i = 0; i < 32; i++) {
        int p = tid + i * 256;            // 0..8191 16B pieces
        int r = p >> 6, q = p & 63;
        int kc = q >> 3, c = q & 7;
        uint32_t dst = sA + kc * 16384 + SWZ(r * 128 + c * 16);
        const char* src = (const char*)A + (size_t)p * 16;
        asm volatile("cp.async.cg.shared.global [%0], [%1], 16;\n" :: "r"(dst), "l"(src));
    }
    asm volatile("cp.async.commit_group;\n");

    // B chunk registers: 4 pieces/thread, 2 float4 each
    float4 breg[8];
    auto ldB = [&](int kt) {
#pragma unroll
        for (int i = 0; i < 4; i++) {
            int p = tid + i * 256;        // 1024 pieces: 128 rows x 8
            int r = p >> 3, c = p & 7;
            int nrow = nblk + r;
            if (nrow < NVT) {
                const float4* src = (const float4*)(B + (size_t)nrow * NH + kt * 64 + c * 8);
                breg[2 * i]     = __ldg(src);
                breg[2 * i + 1] = __ldg(src + 1);
            } else {
                breg[2 * i]     = make_float4(0.f, 0.f, 0.f, 0.f);
                breg[2 * i + 1] = make_float4(0.f, 0.f, 0.f, 0.f);
            }
        }
    };
    auto stB = [&](int buf) {
#pragma unroll
        for (int i = 0; i < 4; i++) {
            int p = tid + i * 256;
            int r = p >> 3, c = p & 7;
            uint32_t dst = sB + buf * 16384 + SWZ(r * 128 + c * 16);
            __nv_bfloat162 h0 = __floats2bfloat162_rn(breg[2*i].x,   breg[2*i].y);
            __nv_bfloat162 h1 = __floats2bfloat162_rn(breg[2*i].z,   breg[2*i].w);
            __nv_bfloat162 h2 = __floats2bfloat162_rn(breg[2*i+1].x, breg[2*i+1].y);
            __nv_bfloat162 h3 = __floats2bfloat162_rn(breg[2*i+1].z, breg[2*i+1].w);
            uint32_t u0 = *(uint32_t*)&h0, u1 = *(uint32_t*)&h1;
            uint32_t u2 = *(uint32_t*)&h2, u3 = *(uint32_t*)&h3;
            asm volatile("st.shared.v4.b32 [%0], {%1,%2,%3,%4};\n"
                         :: "r"(dst), "r"(u0), "r"(u1), "r"(u2), "r"(u3));
        }
    };

    ldB(0);                                  // prefetch chunk 0
    asm volatile("cp.async.wait_group 0;\n"); // A resident
    __syncthreads();

    float acc[4][4][4] = {};

    for (int kt = 0; kt < 8; kt++) {
        stB(kt & 1);                 // regs -> smem (bf16, swizzled)
        if (kt < 7) ldB(kt + 1);     // issue next chunk's LDGs (latency hidden by MMA)
        __syncthreads();             // STS visible; also WAR guard for buf reuse at kt+2
        uint32_t Ab = sA + kt * 16384;
        uint32_t Bb = sB + (kt & 1) * 16384;
#pragma unroll
        for (int ks = 0; ks < 4; ks++) {        // k-steps of 16 within chunk
            uint32_t a[4][4], b[2][4];
#pragma unroll
            for (int mt = 0; mt < 4; mt++) {
                int row = wm * 64 + mt * 16 + (lane & 15);
                uint32_t addr = Ab + SWZ(row * 128 + ks * 32 + ((lane >> 4) * 16));
                asm volatile("ldmatrix.sync.aligned.m8n8.x4.shared.b16 {%0,%1,%2,%3}, [%4];"
                             : "=r"(a[mt][0]), "=r"(a[mt][1]), "=r"(a[mt][2]), "=r"(a[mt][3])
                             : "r"(addr));
            }
#pragma unroll
            for (int h = 0; h < 2; h++) {
                int row = wn * 32 + h * 16 + ((lane >> 4) << 3) + (lane & 7);
                uint32_t addr = Bb + SWZ(row * 128 + ks * 32 + ((lane >> 3) & 1) * 16);
                asm volatile("ldmatrix.sync.aligned.m8n8.x4.shared.b16 {%0,%1,%2,%3}, [%4];"
                             : "=r"(b[h][0]), "=r"(b[h][1]), "=r"(b[h][2]), "=r"(b[h][3])
                             : "r"(addr));
            }
#pragma unroll
            for (int mt = 0; mt < 4; mt++)
#pragma unroll
                for (int nt = 0; nt < 4; nt++) {
                    uint32_t b0 = b[nt >> 1][(nt & 1) * 2];
                    uint32_t b1 = b[nt >> 1][(nt & 1) * 2 + 1];
                    asm volatile(
                        "mma.sync.aligned.m16n8k16.row.col.f32.bf16.bf16.f32 "
                        "{%0,%1,%2,%3}, {%4,%5,%6,%7}, {%8,%9}, {%0,%1,%2,%3};"
                        : "+f"(acc[mt][nt][0]), "+f"(acc[mt][nt][1]),
                          "+f"(acc[mt][nt][2]), "+f"(acc[mt][nt][3])
                        : "r"(a[mt][0]), "r"(a[mt][1]), "r"(a[mt][2]), "r"(a[mt][3]),
                          "r"(b0), "r"(b1));
                }
        }
        __syncthreads();   // all reads of buf done before next stB overwrites sibling
    }

    // epilogue
#pragma unroll
    for (int mt = 0; mt < 4; mt++) {
        int row0 = wm * 64 + mt * 16 + (lane >> 2);
#pragma unroll
        for (int nt = 0; nt < 4; nt++) {
            int col = nblk + wn * 32 + nt * 8 + (lane & 3) * 2;
            if (col < NVT) {
                float b0 = bias[col], b1 = bias[col + 1];
                float2 v0 = make_float2(acc[mt][nt][0] + b0, acc[mt][nt][1] + b1);
                float2 v1 = make_float2(acc[mt][nt][2] + b0, acc[mt][nt][3] + b1);
                *(float2*)&C[(size_t)row0 * NVT + col] = v0;
                *(float2*)&C[(size_t)(row0 + 8) * NVT + col] = v1;
            }
        }
    }
}

// ---------------- single-pass flash attention over (B, T, H) --------------
template <bool STORE_SCORES>
__global__ __launch_bounds__(512)
void attn_kernel(const float* __restrict__ enc,
                 const float* __restrict__ d,
                 float* __restrict__ ctx_out,
                 float* __restrict__ scores_out) {
    int b = blockIdx.x;
    int tid = threadIdx.x, wid = tid >> 5, lane = tid & 31;
    __shared__ float s_s[TT];
    __shared__ float s_m[16], s_l[16];
    __shared__ float s_ctx[NH];
    __shared__ float s_mg, s_lg;

    float dreg[16];
    const float* dp = d + (size_t)b * NH;
#pragma unroll
    for (int q = 0; q < 4; q++) {
        float4 v = *(const float4*)(dp + q * 128 + lane * 4);
        dreg[q * 4 + 0] = v.x; dreg[q * 4 + 1] = v.y;
        dreg[q * 4 + 2] = v.z; dreg[q * 4 + 3] = v.w;
    }

    float m = -INFINITY, l = 0.f, acc[16];
#pragma unroll
    for (int i = 0; i < 16; i++) acc[i] = 0.f;

    const float* ep = enc + (size_t)b * TT * NH;
    int tbeg = wid * 64;
    for (int t0 = tbeg; t0 < tbeg + 64; t0 += 2) {
        float e0[16], e1[16];
        const float* r0 = ep + (size_t)t0 * NH;
        const float* r1 = r0 + NH;
#pragma unroll
        for (int q = 0; q < 4; q++) {
            float4 v0 = *(const float4*)(r0 + q * 128 + lane * 4);
            float4 v1 = *(const float4*)(r1 + q * 128 + lane * 4);
            e0[q*4+0]=v0.x; e0[q*4+1]=v0.y; e0[q*4+2]=v0.z; e0[q*4+3]=v0.w;
            e1[q*4+0]=v1.x; e1[q*4+1]=v1.y; e1[q*4+2]=v1.z; e1[q*4+3]=v1.w;
        }
        float sc0 = 0.f, sc1 = 0.f;
#pragma unroll
        for (int i = 0; i < 16; i++) { sc0 += e0[i] * dreg[i]; sc1 += e1[i] * dreg[i]; }
#pragma unroll
        for (int o = 16; o > 0; o >>= 1) {
            sc0 += __shfl_xor_sync(0xffffffffu, sc0, o);
            sc1 += __shfl_xor_sync(0xffffffffu, sc1, o);
        }
        if (lane == 0) { s_s[t0] = sc0; s_s[t0 + 1] = sc1; }
        {
            float mn = fmaxf(m, sc0);
            float corr = __expf(m - mn);
            float p = __expf(sc0 - mn);
            l = l * corr + p;
#pragma unroll
            for (int i = 0; i < 16; i++) acc[i] = acc[i] * corr + p * e0[i];
            m = mn;
        }
        {
            float mn = fmaxf(m, sc1);
            float corr = __expf(m - mn);
            float p = __expf(sc1 - mn);
            l = l * corr + p;
#pragma unroll
            for (int i = 0; i < 16; i++) acc[i] = acc[i] * corr + p * e1[i];
            m = mn;
        }
    }
    if (lane == 0) { s_m[wid] = m; s_l[wid] = l; }
    for (int i = tid; i < NH; i += 512) s_ctx[i] = 0.f;
    __syncthreads();
    if (tid == 0) {
        float mg = -INFINITY;
#pragma unroll
        for (int w = 0; w < 16; w++) mg = fmaxf(mg, s_m[w]);
        float lg = 0.f;
#pragma unroll
        for (int w = 0; w < 16; w++) lg += s_l[w] * __expf(s_m[w] - mg);
        s_mg = mg; s_lg = lg;
    }
    __syncthreads();
    float f = __expf(m - s_mg);
#pragma unroll
    for (int q = 0; q < 4; q++)
#pragma unroll
        for (int u = 0; u < 4; u++)
            atomicAdd(&s_ctx[q * 128 + lane * 4 + u], acc[q * 4 + u] * f);
    __syncthreads();
    float inv = 1.0f / s_lg;
    for (int i = tid; i < NH; i += 512) ctx_out[(size_t)b * NH + i] = s_ctx[i] * inv;
    if (STORE_SCORES) {
        float mg = s_mg;
        for (int t = tid; t < TT; t += 512)
            scores_out[(size_t)b * TT + t] = __expf(s_s[t] - mg) * inv;
    }
}

// ---------------- scatter-add copy distribution ----------------
__global__ void scatter_kernel(const int* __restrict__ cinp,
                               const float* __restrict__ cscores,
                               float* __restrict__ pcopy) {
    int i = blockIdx.x * blockDim.x + threadIdx.x;
    int b = i >> 10;
    atomicAdd(&pcopy[(size_t)b * NVO + cinp[i]], cscores[i]);
}

// ---------------- p_gen ----------------
__global__ void pgen_kernel(const float* __restrict__ ctx,
                            const float* __restrict__ cctx,
                            const float* __restrict__ dec,
                            const float* __restrict__ x,
                            const float* __restrict__ genW,
                            const float* __restrict__ genb,
                            const float* __restrict__ sigb,
                            const int* __restrict__ cinp,
                            float* __restrict__ pgen) {
    int b = blockIdx.x, tid = threadIdx.x;  // 256 threads
    const int F = 3 * NH + NE;
    float s = 0.f;
    for (int k = tid; k < F; k += 256) {
        float fv;
        if (k < NH)            fv = ctx[b * NH + k];
        else if (k < 2 * NH)   fv = cctx[b * NH + k - NH];
        else if (k < 3 * NH)   fv = dec[b * NH + k - 2 * NH];
        else                   fv = x[b * NE + k - 3 * NH];
        s += genW[k] * fv;
    }
    int cnt = 0;
    for (int t = tid; t < TT; t += 256) cnt += (cinp[b * TT + t] > 0);
    __shared__ float ss[256];
    __shared__ int   sc[256];
    ss[tid] = s; sc[tid] = cnt;
    __syncthreads();
    for (int o = 128; o > 0; o >>= 1) {
        if (tid < o) { ss[tid] += ss[tid + o]; sc[tid] += sc[tid + o]; }
        __syncthreads();
    }
    if (tid == 0) {
        float pg = 1.f / (1.f + __expf(-(ss[0] + genb[0] + sigb[0])));
        if (sc[0] == 0) pg = 1.f;
        pgen[b] = pg;
    }
}

// ---------------- vocab softmax reduction (max + sum) ----------------
__global__ void vred_kernel(const float* __restrict__ logits,
                            float* __restrict__ rmax, float* __restrict__ rsum) {
    int b = blockIdx.x, tid = threadIdx.x;  // 256 threads
    float m = -INFINITY, l = 0.f;
    const float* row = logits + (size_t)b * NVT;
    for (int v = tid; v < NVT; v += 256) {
        float xv = row[v];
        if (xv > m) { l = l * __expf(m - xv) + 1.f; m = xv; }
        else        { l += __expf(xv - m); }
    }
#pragma unroll
    for (int o = 16; o > 0; o >>= 1) {
        float m2 = __shfl_xor_sync(0xffffffffu, m, o);
        float l2 = __shfl_xor_sync(0xffffffffu, l, o);
        float mn = fmaxf(m, m2);
        l = l * __expf(m - mn) + l2 * __expf(m2 - mn);
        m = mn;
    }
    __shared__ float sm[8], sl[8];
    if ((tid & 31) == 0) { sm[tid >> 5] = m; sl[tid >> 5] = l; }
    __syncthreads();
    if (tid == 0) {
        float M = sm[0];
#pragma unroll
        for (int w = 1; w < 8; w++) M = fmaxf(M, sm[w]);
        float Ls = 0.f;
#pragma unroll
        for (int w = 0; w < 8; w++) Ls += sl[w] * __expf(sm[w] - M);
        rmax[b] = M; rsum[b] = Ls;
    }
}

// ---------------- final merge: log(pgen*pvocab + (1-pgen)*pcopy) ----------
__global__ void final_kernel(const float* __restrict__ logits,
                             const float* __restrict__ rmax,
                             const float* __restrict__ rsum,
                             const float* __restrict__ pgen,
                             const float* __restrict__ pcopy,
                             float* __restrict__ out) {
    int i = blockIdx.x * blockDim.x + threadIdx.x;
    if (i >= NB * NVO) return;
    int b = i / NVO;
    int v = i - b * NVO;
    float pg = pgen[b];
    float pv = 0.f;
    if (v < NVT)
        pv = __expf(logits[(size_t)b * NVT + v] - rmax[b]) / rsum[b];
    float p = pg * pv + (1.f - pg) * pcopy[i];
    out[i] = __logf(fmaxf(p, 1e-10f));
}

// ---------------- launcher ----------------
extern "C" void kernel_launch(void* const* d_in, const int* in_sizes, int n_in,
                              void* d_out, int out_size) {
    const int*   ids    = (const int*)d_in[0];
    const float* h0     = (const float*)d_in[1];
    const float* c0     = (const float*)d_in[2];
    const float* enc    = (const float*)d_in[3];
    const float* cenc   = (const float*)d_in[4];
    const int*   cinp   = (const int*)d_in[5];
    const float* emb    = (const float*)d_in[6];
    const float* W_ih   = (const float*)d_in[7];
    const float* W_hh   = (const float*)d_in[8];
    const float* b_ih   = (const float*)d_in[9];
    const float* b_hh   = (const float*)d_in[10];
    const float* attn_W = (const float*)d_in[11];
    const float* attn_b = (const float*)d_in[12];
    const float* cattn_W= (const float*)d_in[13];
    const float* cattn_b= (const float*)d_in[14];
    const float* gen_W  = (const float*)d_in[15];
    const float* gen_b  = (const float*)d_in[16];
    const float* sig_b  = (const float*)d_in[17];
    const float* out_W  = (const float*)d_in[18];
    const float* out_b  = (const float*)d_in[19];
    float* out = (float*)d_out;

    void* sp = nullptr;
    cudaGetSymbolAddress(&sp, g_scratch);
    float* S = (float*)sp;
    float* X      = S + OFF_X;
    float* GATES  = S + OFF_GATES;
    float* DEC    = S + OFF_DEC;
    float* D1     = S + OFF_D1;
    float* D2     = S + OFF_D2;
    float* CTX    = S + OFF_CTX;
    float* CCTX   = S + OFF_CCTX;
    float* CSC    = S + OFF_CSC;
    float* PGEN   = S + OFF_PGEN;
    float* RMAX   = S + OFF_RMAX;
    float* RSUM   = S + OFF_RSUM;
    float* LOGITS = S + OFF_LOGITS;
    float* PCOPY  = S + OFF_PCOPY;
    __nv_bfloat16* DECBF = (__nv_bfloat16*)(S + OFF_DECBF);

    int write_hc = (out_size >= NB * NVO + 2 * NB * NH) ? 1 : 0;

    cudaFuncSetAttribute(logits_mma, cudaFuncAttributeMaxDynamicSharedMemorySize, 164096);

    // 1. zero accumulation buffers: PCOPY, and GATES..D2 span
    zero_kernel<<<2048, 1024>>>(PCOPY, NB * NVO);
    zero_kernel<<<896, 512>>>(GATES, NB * 4 * NH + 3 * NB * NH);
    // 2. embedding
    embed_kernel<<<NB, 256>>>(ids, emb, X);
    // 3. LSTM gates = x @ W_ih^T + h0 @ W_hh^T (split-K atomic)
    gemm_skinny<2><<<dim3(64, 2, 2), 256>>>(X, NE, W_ih, NE, nullptr, GATES, 4 * NH, 4 * NH, NE);
    gemm_skinny<2><<<dim3(64, 2, 2), 256>>>(h0, NH, W_hh, NH, nullptr, GATES, 4 * NH, 4 * NH, NH);
    // 4. LSTM pointwise -> dec, h_new, c_new
    lstm_kernel<<<NB, NH>>>(GATES, c0, b_ih, b_hh, DEC, out, write_hc);
    // 5. dec -> bf16
    f2bf_kernel<<<64, 256>>>((const float4*)DEC, (__nv_bfloat162*)DECBF, NB * NH / 4);
    // 6. logits GEMM on tensor cores (fused fp32->bf16 weight load)
    logits_mma<<<(NVT + 127) / 128, 256, 164096>>>(DECBF, out_W, out_b, LOGITS);
    // 7. d1, d2 projections
    gemm_skinny<4><<<dim3(16, 2, 4), 256>>>(DEC, NH, attn_W, NH, attn_b, D1, NH, NH, NH);
    gemm_skinny<4><<<dim3(16, 2, 4), 256>>>(DEC, NH, cattn_W, NH, cattn_b, D2, NH, NH, NH);
    // 8. attentions (single-pass flash)
    attn_kernel<false><<<NB, 512>>>(enc, D1, CTX, nullptr);
    attn_kernel<true ><<<NB, 512>>>(cenc, D2, CCTX, CSC);
    // 9. scatter copy scores
    scatter_kernel<<<(NB * TT) / 256, 256>>>(cinp, CSC, PCOPY);
    // 10. p_gen
    pgen_kernel<<<NB, 256>>>(CTX, CCTX, DEC, X, gen_W, gen_b, sig_b, cinp, PGEN);
    // 11. vocab softmax stats
    vred_kernel<<<NB, 256>>>(LOGITS, RMAX, RSUM);
    // 12. final merge + log
    final_kernel<<<(NB * NVO + 255) / 256, 256>>>(LOGITS, RMAX, RSUM, PGEN, PCOPY, out);
}

// round 10
// speedup vs baseline: 2.1914x; 1.1025x over previous
#include <cuda_runtime.h>
#include <cuda_bf16.h>
#include <math.h>
#include <stdint.h>

// Problem dims
static const int NB  = 128;
static const int TT  = 1024;   // T == TC
static const int NL  = 4;
static const int NVT = 50000;
static const int NE  = 256;
static const int NH  = 512;
static const int NVO = 50050;  // VT + MAX_OOV

// ---------------- scratch (single __device__ array, offsets in floats) ----
static const size_t OFF_X      = 0;                               // B*E
static const size_t OFF_GATESP = OFF_X      + (size_t)NB*NE;      // 4 * B*4H partials
static const size_t OFF_DEC    = OFF_GATESP + (size_t)4*NB*4*NH;  // B*H
static const size_t OFF_D1P    = OFF_DEC    + (size_t)NB*NH;      // 4 * B*H partials
static const size_t OFF_D2P    = OFF_D1P    + (size_t)4*NB*NH;    // 4 * B*H partials
static const size_t OFF_CTX    = OFF_D2P    + (size_t)4*NB*NH;
static const size_t OFF_CCTX   = OFF_CTX    + (size_t)NB*NH;
static const size_t OFF_CSC    = OFF_CCTX   + (size_t)NB*NH;      // B*TC
static const size_t OFF_PGEN   = OFF_CSC    + (size_t)NB*TT;      // B
static const size_t OFF_RMAX   = OFF_PGEN   + NB;                 // B
static const size_t OFF_RSUM   = OFF_RMAX   + NB;                 // B
static const size_t OFF_PAD    = OFF_RSUM   + NB + 64;
static const size_t OFF_LOGITS = (OFF_PAD + 63) & ~(size_t)63;    // B*VT
static const size_t OFF_PCOPY  = OFF_LOGITS + (size_t)NB*NVT;     // B*VO
static const size_t OFF_DECBF  = ((OFF_PCOPY + (size_t)NB*NVO) + 63) & ~(size_t)63;  // B*NH bf16
static const size_t SCRATCH_SZ = OFF_DECBF + (size_t)NB*NH/2 + 64;

__device__ float g_scratch[SCRATCH_SZ];

#define SWZ(o) ((o) ^ (((o) >> 3) & 0x70))

// ---------------- zero ----------------
__global__ void zero_kernel(float* p, int n) {
    for (int i = blockIdx.x * blockDim.x + threadIdx.x; i < n; i += gridDim.x * blockDim.x)
        p[i] = 0.f;
}

// ---------------- embed: x = tanh(mean of 4 emb rows) ----------------
__global__ void embed_kernel(const int* __restrict__ ids,
                             const float* __restrict__ emb,
                             float* __restrict__ x_out) {
    int b = blockIdx.x, e = threadIdx.x;   // 256 threads
    float s = 0.f;
#pragma unroll
    for (int l = 0; l < NL; l++)
        s += emb[(size_t)ids[b * NL + l] * NE + e];
    x_out[b * NE + e] = tanhf(s * (1.0f / NL));
}

// ---------------- fused LSTM-gates GEMM over concatenated K=768 ----------
// GATESP[z][128 x 2048], z = blockIdx.z in [0,4): k-range [z*192, z*192+192).
// k<256 pulls from X/W_ih, k>=256 from h0/W_hh (16-step never crosses 256).
// No atomics: each z writes its own partial buffer; lstm_kernel sums them.
__global__ __launch_bounds__(256)
void gates_gemm(const float* __restrict__ X,
                const float* __restrict__ h0,
                const float* __restrict__ W_ih,
                const float* __restrict__ W_hh,
                float* __restrict__ GP) {
    __shared__ float As[16][65];
    __shared__ float Ws[16][33];
    int tid = threadIdx.x;
    int tm = tid & 15;
    int tn = tid >> 4;
    int mb = blockIdx.y * 64;
    int jb = blockIdx.x * 32;
    int z  = blockIdx.z;

    float acc[4][2] = {};
    for (int k0 = z * 192; k0 < z * 192 + 192; k0 += 16) {
        const float* A; const float* W; int ld, kk0;
        if (k0 < NE) { A = X;  W = W_ih; ld = NE; kk0 = k0; }
        else         { A = h0; W = W_hh; ld = NH; kk0 = k0 - NE; }
        __syncthreads();
#pragma unroll
        for (int i = 0; i < 4; i++) {
            int idx = tid + i * 256;
            int row = idx >> 4, kk = idx & 15;
            As[kk][row] = A[(size_t)(mb + row) * ld + kk0 + kk];
        }
#pragma unroll
        for (int i = 0; i < 2; i++) {
            int idx = tid + i * 256;
            int j = idx >> 4, kk = idx & 15;
            Ws[kk][j] = W[(size_t)(jb + j) * ld + kk0 + kk];
        }
        __syncthreads();
#pragma unroll
        for (int k = 0; k < 16; k++) {
            float a[4], w0 = Ws[k][tn * 2], w1 = Ws[k][tn * 2 + 1];
#pragma unroll
            for (int r = 0; r < 4; r++) a[r] = As[k][tm + 16 * r];
#pragma unroll
            for (int r = 0; r < 4; r++) { acc[r][0] += a[r] * w0; acc[r][1] += a[r] * w1; }
        }
    }
    float* out = GP + (size_t)z * NB * 4 * NH;
#pragma unroll
    for (int r = 0; r < 4; r++)
#pragma unroll
        for (int u = 0; u < 2; u++)
            out[(size_t)(mb + tm + 16 * r) * 4 * NH + jb + tn * 2 + u] = acc[r][u];
}

// ---------------- LSTM pointwise: sums 4 gate partials, emits DEC+DECBF ----
__device__ __forceinline__ float sigm(float x) { return 1.f / (1.f + __expf(-x)); }

__global__ void lstm_kernel(const float* __restrict__ GP,
                            const float* __restrict__ c0,
                            const float* __restrict__ b_ih,
                            const float* __restrict__ b_hh,
                            float* __restrict__ dec,
                            __nv_bfloat16* __restrict__ decbf,
                            float* __restrict__ out, int write_hc) {
    int b = blockIdx.x, j = threadIdx.x;  // 512 threads
    const size_t S = (size_t)NB * 4 * NH;
    size_t base = (size_t)b * 4 * NH;
    float ig = b_ih[j]          + b_hh[j];
    float fg = b_ih[NH + j]     + b_hh[NH + j];
    float gg = b_ih[2*NH + j]   + b_hh[2*NH + j];
    float og = b_ih[3*NH + j]   + b_hh[3*NH + j];
#pragma unroll
    for (int z = 0; z < 4; z++) {
        const float* g = GP + z * S + base;
        ig += g[j];
        fg += g[NH + j];
        gg += g[2 * NH + j];
        og += g[3 * NH + j];
    }
    float c = sigm(fg) * c0[b * NH + j] + sigm(ig) * tanhf(gg);
    float h = sigm(og) * tanhf(c);
    dec[b * NH + j] = h;
    decbf[b * NH + j] = __float2bfloat16(h);
    if (write_hc) {
        out[(size_t)NB * NVO + (size_t)b * NH + j] = h;
        out[(size_t)NB * NVO + (size_t)NB * NH + (size_t)b * NH + j] = c;
    }
}

// ---------------- logits GEMM via bf16 mma.sync, fused fp32->bf16 B load --
// C[128 x 50000] = A[128x512]bf16 @ B[50000x512]fp32^T + bias, fp32 accum.
__global__ __launch_bounds__(256, 1)
void logits_mma(const __nv_bfloat16* __restrict__ A,
                const float* __restrict__ B,
                const float* __restrict__ bias,
                float* __restrict__ C) {
    extern __shared__ char smem[];
    const int tid = threadIdx.x, lane = tid & 31, wid = tid >> 5;
    const int wm = wid >> 2, wn = wid & 3;
    const int nblk = blockIdx.x * 128;
    uint32_t sA = (uint32_t)__cvta_generic_to_shared(smem);
    uint32_t sB = sA + 131072;

    // stage all of A: 8 chunks of [128 rows][128B], swizzled
#pragma unroll
    for (int i = 0; i < 32; i++) {
        int p = tid + i * 256;            // 0..8191 16B pieces
        int r = p >> 6, q = p & 63;
        int kc = q >> 3, c = q & 7;
        uint32_t dst = sA + kc * 16384 + SWZ(r * 128 + c * 16);
        const char* src = (const char*)A + (size_t)p * 16;
        asm volatile("cp.async.cg.shared.global [%0], [%1], 16;\n" :: "r"(dst), "l"(src));
    }
    asm volatile("cp.async.commit_group;\n");

    float4 breg[8];
    auto ldB = [&](int kt) {
#pragma unroll
        for (int i = 0; i < 4; i++) {
            int p = tid + i * 256;        // 1024 pieces: 128 rows x 8
            int r = p >> 3, c = p & 7;
            int nrow = nblk + r;
            if (nrow < NVT) {
                const float4* src = (const float4*)(B + (size_t)nrow * NH + kt * 64 + c * 8);
                breg[2 * i]     = __ldg(src);
                breg[2 * i + 1] = __ldg(src + 1);
            } else {
                breg[2 * i]     = make_float4(0.f, 0.f, 0.f, 0.f);
                breg[2 * i + 1] = make_float4(0.f, 0.f, 0.f, 0.f);
            }
        }
    };
    auto stB = [&](int buf) {
#pragma unroll
        for (int i = 0; i < 4; i++) {
            int p = tid + i * 256;
            int r = p >> 3, c = p & 7;
            uint32_t dst = sB + buf * 16384 + SWZ(r * 128 + c * 16);
            __nv_bfloat162 h0 = __floats2bfloat162_rn(breg[2*i].x,   breg[2*i].y);
            __nv_bfloat162 h1 = __floats2bfloat162_rn(breg[2*i].z,   breg[2*i].w);
            __nv_bfloat162 h2 = __floats2bfloat162_rn(breg[2*i+1].x, breg[2*i+1].y);
            __nv_bfloat162 h3 = __floats2bfloat162_rn(breg[2*i+1].z, breg[2*i+1].w);
            uint32_t u0 = *(uint32_t*)&h0, u1 = *(uint32_t*)&h1;
            uint32_t u2 = *(uint32_t*)&h2, u3 = *(uint32_t*)&h3;
            asm volatile("st.shared.v4.b32 [%0], {%1,%2,%3,%4};\n"
                         :: "r"(dst), "r"(u0), "r"(u1), "r"(u2), "r"(u3));
        }
    };

    ldB(0);
    asm volatile("cp.async.wait_group 0;\n");
    __syncthreads();

    float acc[4][4][4] = {};

    for (int kt = 0; kt < 8; kt++) {
        stB(kt & 1);
        if (kt < 7) ldB(kt + 1);
        __syncthreads();
        uint32_t Ab = sA + kt * 16384;
        uint32_t Bb = sB + (kt & 1) * 16384;
#pragma unroll
        for (int ks = 0; ks < 4; ks++) {
            uint32_t a[4][4], b[2][4];
#pragma unroll
            for (int mt = 0; mt < 4; mt++) {
                int row = wm * 64 + mt * 16 + (lane & 15);
                uint32_t addr = Ab + SWZ(row * 128 + ks * 32 + ((lane >> 4) * 16));
                asm volatile("ldmatrix.sync.aligned.m8n8.x4.shared.b16 {%0,%1,%2,%3}, [%4];"
                             : "=r"(a[mt][0]), "=r"(a[mt][1]), "=r"(a[mt][2]), "=r"(a[mt][3])
                             : "r"(addr));
            }
#pragma unroll
            for (int h = 0; h < 2; h++) {
                int row = wn * 32 + h * 16 + ((lane >> 4) << 3) + (lane & 7);
                uint32_t addr = Bb + SWZ(row * 128 + ks * 32 + ((lane >> 3) & 1) * 16);
                asm volatile("ldmatrix.sync.aligned.m8n8.x4.shared.b16 {%0,%1,%2,%3}, [%4];"
                             : "=r"(b[h][0]), "=r"(b[h][1]), "=r"(b[h][2]), "=r"(b[h][3])
                             : "r"(addr));
            }
#pragma unroll
            for (int mt = 0; mt < 4; mt++)
#pragma unroll
                for (int nt = 0; nt < 4; nt++) {
                    uint32_t b0 = b[nt >> 1][(nt & 1) * 2];
                    uint32_t b1 = b[nt >> 1][(nt & 1) * 2 + 1];
                    asm volatile(
                        "mma.sync.aligned.m16n8k16.row.col.f32.bf16.bf16.f32 "
                        "{%0,%1,%2,%3}, {%4,%5,%6,%7}, {%8,%9}, {%0,%1,%2,%3};"
                        : "+f"(acc[mt][nt][0]), "+f"(acc[mt][nt][1]),
                          "+f"(acc[mt][nt][2]), "+f"(acc[mt][nt][3])
                        : "r"(a[mt][0]), "r"(a[mt][1]), "r"(a[mt][2]), "r"(a[mt][3]),
                          "r"(b0), "r"(b1));
                }
        }
        __syncthreads();
    }

    // epilogue
#pragma unroll
    for (int mt = 0; mt < 4; mt++) {
        int row0 = wm * 64 + mt * 16 + (lane >> 2);
#pragma unroll
        for (int nt = 0; nt < 4; nt++) {
            int col = nblk + wn * 32 + nt * 8 + (lane & 3) * 2;
            if (col < NVT) {
                float b0 = bias[col], b1 = bias[col + 1];
                float2 v0 = make_float2(acc[mt][nt][0] + b0, acc[mt][nt][1] + b1);
                float2 v1 = make_float2(acc[mt][nt][2] + b0, acc[mt][nt][3] + b1);
                *(float2*)&C[(size_t)row0 * NVT + col] = v0;
                *(float2*)&C[(size_t)(row0 + 8) * NVT + col] = v1;
            }
        }
    }
}

// ---------------- fused d1/d2 projections, split-K=4 partial buffers -------
// grid (16, 2, 8): z&3 = k-chunk, z>>2 = which (0: attn, 1: cattn).
// Bias folded into chunk 0. Partials summed at consumption (attn2 dreg load).
__global__ __launch_bounds__(256)
void dproj_gemm(const float* __restrict__ DEC,
                const float* __restrict__ attn_W, const float* __restrict__ attn_b,
                const float* __restrict__ cattn_W, const float* __restrict__ cattn_b,
                float* __restrict__ D1P, float* __restrict__ D2P) {
    __shared__ float As[16][65];
    __shared__ float Ws[16][33];
    int tid = threadIdx.x;
    int tm = tid & 15;
    int tn = tid >> 4;
    int mb = blockIdx.y * 64;
    int jb = blockIdx.x * 32;
    int z     = blockIdx.z & 3;
    int which = blockIdx.z >> 2;
    const float* W    = which ? cattn_W : attn_W;
    const float* bias = which ? cattn_b : attn_b;
    float* OUT = (which ? D2P : D1P) + (size_t)z * NB * NH;

    float acc[4][2] = {};
    for (int k0 = z * 128; k0 < z * 128 + 128; k0 += 16) {
        __syncthreads();
#pragma unroll
        for (int i = 0; i < 4; i++) {
            int idx = tid + i * 256;
            int row = idx >> 4, kk = idx & 15;
            As[kk][row] = DEC[(size_t)(mb + row) * NH + k0 + kk];
        }
#pragma unroll
        for (int i = 0; i < 2; i++) {
            int idx = tid + i * 256;
            int j = idx >> 4, kk = idx & 15;
            Ws[kk][j] = W[(size_t)(jb + j) * NH + k0 + kk];
        }
        __syncthreads();
#pragma unroll
        for (int k = 0; k < 16; k++) {
            float a[4], w0 = Ws[k][tn * 2], w1 = Ws[k][tn * 2 + 1];
#pragma unroll
            for (int r = 0; r < 4; r++) a[r] = As[k][tm + 16 * r];
#pragma unroll
            for (int r = 0; r < 4; r++) { acc[r][0] += a[r] * w0; acc[r][1] += a[r] * w1; }
        }
    }
#pragma unroll
    for (int r = 0; r < 4; r++)
#pragma unroll
        for (int u = 0; u < 2; u++) {
            int j = jb + tn * 2 + u;
            float v = acc[r][u];
            if (z == 0) v += bias[j];
            OUT[(size_t)(mb + tm + 16 * r) * NH + j] = v;
        }
}

// ---------------- fused dual flash attention (256 blocks) ------------------
// blockIdx.x < 128: source attention (enc, D1P -> ctx).
// blockIdx.x >= 128: context attention (cenc, D2P -> cctx + scores).
__global__ __launch_bounds__(512)
void attn2_kernel(const float* __restrict__ enc,
                  const float* __restrict__ cenc,
                  const float* __restrict__ D1P,
                  const float* __restrict__ D2P,
                  float* __restrict__ ctx,
                  float* __restrict__ cctx,
                  float* __restrict__ scores_out) {
    int which = blockIdx.x >> 7;
    int b = blockIdx.x & 127;
    int tid = threadIdx.x, wid = tid >> 5, lane = tid & 31;
    __shared__ float s_s[TT];
    __shared__ float s_m[16], s_l[16];
    __shared__ float s_ctx[NH];
    __shared__ float s_mg, s_lg;

    const float* ep_base = which ? cenc : enc;
    const float* dp      = (which ? D2P : D1P) + (size_t)b * NH;
    float* ctx_out       = (which ? cctx : ctx) + (size_t)b * NH;

    // d vector = sum of 4 split-K partials
    float dreg[16];
#pragma unroll
    for (int q = 0; q < 4; q++) {
        float4 v = *(const float4*)(dp + q * 128 + lane * 4);
#pragma unroll
        for (int z = 1; z < 4; z++) {
            float4 w = *(const float4*)(dp + (size_t)z * NB * NH + q * 128 + lane * 4);
            v.x += w.x; v.y += w.y; v.z += w.z; v.w += w.w;
        }
        dreg[q * 4 + 0] = v.x; dreg[q * 4 + 1] = v.y;
        dreg[q * 4 + 2] = v.z; dreg[q * 4 + 3] = v.w;
    }

    float m = -INFINITY, l = 0.f, acc[16];
#pragma unroll
    for (int i = 0; i < 16; i++) acc[i] = 0.f;

    const float* ep = ep_base + (size_t)b * TT * NH;
    int tbeg = wid * 64;
    for (int t0 = tbeg; t0 < tbeg + 64; t0 += 2) {
        float e0[16], e1[16];
        const float* r0 = ep + (size_t)t0 * NH;
        const float* r1 = r0 + NH;
#pragma unroll
        for (int q = 0; q < 4; q++) {
            float4 v0 = *(const float4*)(r0 + q * 128 + lane * 4);
            float4 v1 = *(const float4*)(r1 + q * 128 + lane * 4);
            e0[q*4+0]=v0.x; e0[q*4+1]=v0.y; e0[q*4+2]=v0.z; e0[q*4+3]=v0.w;
            e1[q*4+0]=v1.x; e1[q*4+1]=v1.y; e1[q*4+2]=v1.z; e1[q*4+3]=v1.w;
        }
        float sc0 = 0.f, sc1 = 0.f;
#pragma unroll
        for (int i = 0; i < 16; i++) { sc0 += e0[i] * dreg[i]; sc1 += e1[i] * dreg[i]; }
#pragma unroll
        for (int o = 16; o > 0; o >>= 1) {
            sc0 += __shfl_xor_sync(0xffffffffu, sc0, o);
            sc1 += __shfl_xor_sync(0xffffffffu, sc1, o);
        }
        if (lane == 0) { s_s[t0] = sc0; s_s[t0 + 1] = sc1; }
        {
            float mn = fmaxf(m, sc0);
            float corr = __expf(m - mn);
            float p = __expf(sc0 - mn);
            l = l * corr + p;
#pragma unroll
            for (int i = 0; i < 16; i++) acc[i] = acc[i] * corr + p * e0[i];
            m = mn;
        }
        {
            float mn = fmaxf(m, sc1);
            float corr = __expf(m - mn);
            float p = __expf(sc1 - mn);
            l = l * corr + p;
#pragma unroll
            for (int i = 0; i < 16; i++) acc[i] = acc[i] * corr + p * e1[i];
            m = mn;
        }
    }
    if (lane == 0) { s_m[wid] = m; s_l[wid] = l; }
    for (int i = tid; i < NH; i += 512) s_ctx[i] = 0.f;
    __syncthreads();
    if (tid == 0) {
        float mg = -INFINITY;
#pragma unroll
        for (int w = 0; w < 16; w++) mg = fmaxf(mg, s_m[w]);
        float lg = 0.f;
#pragma unroll
        for (int w = 0; w < 16; w++) lg += s_l[w] * __expf(s_m[w] - mg);
        s_mg = mg; s_lg = lg;
    }
    __syncthreads();
    float f = __expf(m - s_mg);
#pragma unroll
    for (int q = 0; q < 4; q++)
#pragma unroll
        for (int u = 0; u < 4; u++)
            atomicAdd(&s_ctx[q * 128 + lane * 4 + u], acc[q * 4 + u] * f);
    __syncthreads();
    float inv = 1.0f / s_lg;
    for (int i = tid; i < NH; i += 512) ctx_out[i] = s_ctx[i] * inv;
    if (which) {
        float mg = s_mg;
        for (int t = tid; t < TT; t += 512)
            scores_out[(size_t)b * TT + t] = __expf(s_s[t] - mg) * inv;
    }
}

// ---------------- scatter-add copy distribution ----------------
__global__ void scatter_kernel(const int* __restrict__ cinp,
                               const float* __restrict__ cscores,
                               float* __restrict__ pcopy) {
    int i = blockIdx.x * blockDim.x + threadIdx.x;
    int b = i >> 10;
    atomicAdd(&pcopy[(size_t)b * NVO + cinp[i]], cscores[i]);
}

// ---------------- p_gen ----------------
__global__ void pgen_kernel(const float* __restrict__ ctx,
                            const float* __restrict__ cctx,
                            const float* __restrict__ dec,
                            const float* __restrict__ x,
                            const float* __restrict__ genW,
                            const float* __restrict__ genb,
                            const float* __restrict__ sigb,
                            const int* __restrict__ cinp,
                            float* __restrict__ pgen) {
    int b = blockIdx.x, tid = threadIdx.x;  // 256 threads
    const int F = 3 * NH + NE;
    float s = 0.f;
    for (int k = tid; k < F; k += 256) {
        float fv;
        if (k < NH)            fv = ctx[b * NH + k];
        else if (k < 2 * NH)   fv = cctx[b * NH + k - NH];
        else if (k < 3 * NH)   fv = dec[b * NH + k - 2 * NH];
        else                   fv = x[b * NE + k - 3 * NH];
        s += genW[k] * fv;
    }
    int cnt = 0;
    for (int t = tid; t < TT; t += 256) cnt += (cinp[b * TT + t] > 0);
    __shared__ float ss[256];
    __shared__ int   sc[256];
    ss[tid] = s; sc[tid] = cnt;
    __syncthreads();
    for (int o = 128; o > 0; o >>= 1) {
        if (tid < o) { ss[tid] += ss[tid + o]; sc[tid] += sc[tid + o]; }
        __syncthreads();
    }
    if (tid == 0) {
        float pg = 1.f / (1.f + __expf(-(ss[0] + genb[0] + sigb[0])));
        if (sc[0] == 0) pg = 1.f;
        pgen[b] = pg;
    }
}

// ---------------- vocab softmax reduction (max + sum) ----------------
__global__ void vred_kernel(const float* __restrict__ logits,
                            float* __restrict__ rmax, float* __restrict__ rsum) {
    int b = blockIdx.x, tid = threadIdx.x;  // 256 threads
    float m = -INFINITY, l = 0.f;
    const float* row = logits + (size_t)b * NVT;
    for (int v = tid; v < NVT; v += 256) {
        float xv = row[v];
        if (xv > m) { l = l * __expf(m - xv) + 1.f; m = xv; }
        else        { l += __expf(xv - m); }
    }
#pragma unroll
    for (int o = 16; o > 0; o >>= 1) {
        float m2 = __shfl_xor_sync(0xffffffffu, m, o);
        float l2 = __shfl_xor_sync(0xffffffffu, l, o);
        float mn = fmaxf(m, m2);
        l = l * __expf(m - mn) + l2 * __expf(m2 - mn);
        m = mn;
    }
    __shared__ float sm[8], sl[8];
    if ((tid & 31) == 0) { sm[tid >> 5] = m; sl[tid >> 5] = l; }
    __syncthreads();
    if (tid == 0) {
        float M = sm[0];
#pragma unroll
        for (int w = 1; w < 8; w++) M = fmaxf(M, sm[w]);
        float Ls = 0.f;
#pragma unroll
        for (int w = 0; w < 8; w++) Ls += sl[w] * __expf(sm[w] - M);
        rmax[b] = M; rsum[b] = Ls;
    }
}

// ---------------- final merge: log(pgen*pvocab + (1-pgen)*pcopy) ----------
__global__ void final_kernel(const float* __restrict__ logits,
                             const float* __restrict__ rmax,
                             const float* __restrict__ rsum,
                             const float* __restrict__ pgen,
                             const float* __restrict__ pcopy,
                             float* __restrict__ out) {
    int i = blockIdx.x * blockDim.x + threadIdx.x;
    if (i >= NB * NVO) return;
    int b = i / NVO;
    int v = i - b * NVO;
    float pg = pgen[b];
    float pv = 0.f;
    if (v < NVT)
        pv = __expf(logits[(size_t)b * NVT + v] - rmax[b]) / rsum[b];
    float p = pg * pv + (1.f - pg) * pcopy[i];
    out[i] = __logf(fmaxf(p, 1e-10f));
}

// ---------------- launcher ----------------
extern "C" void kernel_launch(void* const* d_in, const int* in_sizes, int n_in,
                              void* d_out, int out_size) {
    const int*   ids    = (const int*)d_in[0];
    const float* h0     = (const float*)d_in[1];
    const float* c0     = (const float*)d_in[2];
    const float* enc    = (const float*)d_in[3];
    const float* cenc   = (const float*)d_in[4];
    const int*   cinp   = (const int*)d_in[5];
    const float* emb    = (const float*)d_in[6];
    const float* W_ih   = (const float*)d_in[7];
    const float* W_hh   = (const float*)d_in[8];
    const float* b_ih   = (const float*)d_in[9];
    const float* b_hh   = (const float*)d_in[10];
    const float* attn_W = (const float*)d_in[11];
    const float* attn_b = (const float*)d_in[12];
    const float* cattn_W= (const float*)d_in[13];
    const float* cattn_b= (const float*)d_in[14];
    const float* gen_W  = (const float*)d_in[15];
    const float* gen_b  = (const float*)d_in[16];
    const float* sig_b  = (const float*)d_in[17];
    const float* out_W  = (const float*)d_in[18];
    const float* out_b  = (const float*)d_in[19];
    float* out = (float*)d_out;

    void* sp = nullptr;
    cudaGetSymbolAddress(&sp, g_scratch);
    float* S = (float*)sp;
    float* X      = S + OFF_X;
    float* GATESP = S + OFF_GATESP;
    float* DEC    = S + OFF_DEC;
    float* D1P    = S + OFF_D1P;
    float* D2P    = S + OFF_D2P;
    float* CTX    = S + OFF_CTX;
    float* CCTX   = S + OFF_CCTX;
    float* CSC    = S + OFF_CSC;
    float* PGEN   = S + OFF_PGEN;
    float* RMAX   = S + OFF_RMAX;
    float* RSUM   = S + OFF_RSUM;
    float* LOGITS = S + OFF_LOGITS;
    float* PCOPY  = S + OFF_PCOPY;
    __nv_bfloat16* DECBF = (__nv_bfloat16*)(S + OFF_DECBF);

    int write_hc = (out_size >= NB * NVO + 2 * NB * NH) ? 1 : 0;

    cudaFuncSetAttribute(logits_mma, cudaFuncAttributeMaxDynamicSharedMemorySize, 164096);

    // 0. embedding
    embed_kernel<<<NB, 256>>>(ids, emb, X);
    // 1. fused LSTM-gates GEMM over K=768, 4 partial buffers (no atomics)
    gates_gemm<<<dim3(64, 2, 4), 256>>>(X, h0, W_ih, W_hh, GATESP);
    // 2. LSTM pointwise: sum partials -> dec (fp32 + bf16), h_new, c_new
    lstm_kernel<<<NB, NH>>>(GATESP, c0, b_ih, b_hh, DEC, DECBF, out, write_hc);
    // 3. logits GEMM on tensor cores (ncu capture slot)
    logits_mma<<<(NVT + 127) / 128, 256, 164096>>>(DECBF, out_W, out_b, LOGITS);
    // 4. fused d1/d2 projections (split-K partial buffers)
    dproj_gemm<<<dim3(16, 2, 8), 256>>>(DEC, attn_W, attn_b, cattn_W, cattn_b, D1P, D2P);
    // 5. both attentions in one launch (256 blocks)
    attn2_kernel<<<2 * NB, 512>>>(enc, cenc, D1P, D2P, CTX, CCTX, CSC);
    // 6. zero copy-distribution buffer
    zero_kernel<<<2048, 1024>>>(PCOPY, NB * NVO);
    // 7. scatter copy scores
    scatter_kernel<<<(NB * TT) / 256, 256>>>(cinp, CSC, PCOPY);
    // 8. p_gen
    pgen_kernel<<<NB, 256>>>(CTX, CCTX, DEC, X, gen_W, gen_b, sig_b, cinp, PGEN);
    // 9. vocab softmax stats
    vred_kernel<<<NB, 256>>>(LOGITS, RMAX, RSUM);
    // 10. final merge + log
    final_kernel<<<(NB * NVO + 255) / 256, 256>>>(LOGITS, RMAX, RSUM, PGEN, PCOPY, out);
}